// round 7
// baseline (speedup 1.0000x reference)
#include <cuda_runtime.h>
#include <cuda_fp16.h>
#include <cstdint>

// BMM_S8T_S8N_F16T: hybrid IMMA (cols 0..63) + dp4a (cols 64..127) per 16-row
// warp slab, with K split into two 64-wide halves, double-buffered smem, and
// the half-1 global loads software-pipelined under half-0 compute.
// out[b,m,n] = f32( fp16_round( alpha * sum_k a[b,m,k]*b[b,n,k] ) )

#define BATCH 64
#define MDIM 1024
#define NDIM 1024
#define KDIM 128

#define BM 128
#define BN 128
#define ROWSTRIDE 20        // 16 k-words + 4 pad -> conflict-free for all patterns

#define PACK4(v) __byte_perm(__byte_perm((v).x, (v).y, 0x0040), \
                             __byte_perm((v).z, (v).w, 0x0040), 0x5410)

__global__ __launch_bounds__(256, 2)
void bmm_s8_pipe_kernel(const int* __restrict__ A,
                        const int* __restrict__ Bmat,
                        const float* __restrict__ alpha_p,
                        float* __restrict__ Out) {
    __shared__ uint32_t As[2][BM * ROWSTRIDE];
    __shared__ uint32_t Bs[2][BN * ROWSTRIDE];

    const int tid  = threadIdx.x;
    const int lane = tid & 31;
    const int wid  = tid >> 5;

    const int bn = blockIdx.x;
    const int bm = blockIdx.y;
    const int bz = blockIdx.z;

    const int* Abase = A    + ((size_t)bz * MDIM + (size_t)bm * BM) * KDIM;
    const int* Bbase = Bmat + ((size_t)bz * NDIM + (size_t)bn * BN) * KDIM;

    // ---- Prologue: load K-half 0 (words 0..15) ----
    #pragma unroll
    for (int i = 0; i < 8; i++) {
        int idx = tid + i * 256;
        int row = idx >> 4;          // 0..127
        int col = idx & 15;          // word 0..15
        int4 va = *(const int4*)(Abase + row * KDIM + col * 4);
        As[0][row * ROWSTRIDE + col] = PACK4(va);
        int4 vb = *(const int4*)(Bbase + row * KDIM + col * 4);
        Bs[0][row * ROWSTRIDE + col] = PACK4(vb);
    }
    __syncthreads();

    const int rb = wid * 16;     // warp slab rows
    const int lq = lane >> 2;    // mma group 0..7
    const int lr = lane & 3;     // mma thread-in-group
    const int g  = lane >> 3;    // dp4a row interleave 0..3
    const int j  = lane & 7;     // dp4a col interleave 0..7

    int macc[8][4];
    #pragma unroll
    for (int ni = 0; ni < 8; ni++)
        #pragma unroll
        for (int r = 0; r < 4; r++) macc[ni][r] = 0;

    int dacc[4][8];
    #pragma unroll
    for (int mi = 0; mi < 4; mi++)
        #pragma unroll
        for (int ni = 0; ni < 8; ni++) dacc[mi][ni] = 0;

    // compute one 32-wide k-step (ksl in {0,1}) on buffer BUF
    #define COMPUTE_KS(BUF, KSL) do {                                          \
        uint32_t af[4];                                                        \
        {                                                                      \
            const uint32_t* p = &As[BUF][(rb + lq) * ROWSTRIDE + (KSL)*8 + lr];\
            af[0] = p[0];  af[2] = p[4];                                       \
            const uint32_t* p8 = p + 8 * ROWSTRIDE;                            \
            af[1] = p8[0]; af[3] = p8[4];                                      \
        }                                                                      \
        _Pragma("unroll")                                                      \
        for (int ni = 0; ni < 8; ni++) {                                       \
            const uint32_t* p = &Bs[BUF][(ni*8 + lq) * ROWSTRIDE + (KSL)*8 + lr];\
            uint32_t b0 = p[0], b1 = p[4];                                     \
            asm volatile(                                                      \
                "mma.sync.aligned.m16n8k32.row.col.s32.s8.s8.s32 "             \
                "{%0,%1,%2,%3}, {%4,%5,%6,%7}, {%8,%9}, {%0,%1,%2,%3};"        \
                : "+r"(macc[ni][0]), "+r"(macc[ni][1]),                        \
                  "+r"(macc[ni][2]), "+r"(macc[ni][3])                         \
                : "r"(af[0]), "r"(af[1]), "r"(af[2]), "r"(af[3]),              \
                  "r"(b0), "r"(b1));                                           \
        }                                                                      \
        _Pragma("unroll")                                                      \
        for (int c = 0; c < 2; c++) {                                          \
            const int kw = (KSL)*8 + c*4;                                      \
            uint4 av[4];                                                       \
            _Pragma("unroll")                                                  \
            for (int mi = 0; mi < 4; mi++)                                     \
                av[mi] = *(const uint4*)&As[BUF][(rb + g + 4*mi)*ROWSTRIDE + kw];\
            _Pragma("unroll")                                                  \
            for (int ni = 0; ni < 8; ni++) {                                   \
                uint4 bv = *(const uint4*)&Bs[BUF][(64 + j + 8*ni)*ROWSTRIDE + kw];\
                _Pragma("unroll")                                              \
                for (int mi = 0; mi < 4; mi++) {                               \
                    int v = dacc[mi][ni];                                      \
                    v = __dp4a((int)av[mi].x, (int)bv.x, v);                   \
                    v = __dp4a((int)av[mi].y, (int)bv.y, v);                   \
                    v = __dp4a((int)av[mi].z, (int)bv.z, v);                   \
                    v = __dp4a((int)av[mi].w, (int)bv.w, v);                   \
                    dacc[mi][ni] = v;                                          \
                }                                                              \
            }                                                                  \
        }                                                                      \
    } while (0)

    // ---- Pipelined half-1 load under half-0 compute ----
    int4 sa[4], sb[4];

    // batch 0 LDGs (words 16..23 region: iterations 0..3)
    #pragma unroll
    for (int i = 0; i < 4; i++) {
        int idx = tid + i * 256;
        int row = idx >> 4, col = idx & 15;
        sa[i] = *(const int4*)(Abase + row * KDIM + 64 + col * 4);
        sb[i] = *(const int4*)(Bbase + row * KDIM + 64 + col * 4);
    }

    COMPUTE_KS(0, 0);

    #pragma unroll
    for (int i = 0; i < 4; i++) {
        int idx = tid + i * 256;
        int row = idx >> 4, col = idx & 15;
        As[1][row * ROWSTRIDE + col] = PACK4(sa[i]);
        Bs[1][row * ROWSTRIDE + col] = PACK4(sb[i]);
    }

    // batch 1 LDGs (iterations 4..7)
    #pragma unroll
    for (int i = 0; i < 4; i++) {
        int idx = tid + (i + 4) * 256;
        int row = idx >> 4, col = idx & 15;
        sa[i] = *(const int4*)(Abase + row * KDIM + 64 + col * 4);
        sb[i] = *(const int4*)(Bbase + row * KDIM + 64 + col * 4);
    }

    COMPUTE_KS(0, 1);

    #pragma unroll
    for (int i = 0; i < 4; i++) {
        int idx = tid + (i + 4) * 256;
        int row = idx >> 4, col = idx & 15;
        As[1][row * ROWSTRIDE + col] = PACK4(sa[i]);
        Bs[1][row * ROWSTRIDE + col] = PACK4(sb[i]);
    }

    __syncthreads();

    COMPUTE_KS(1, 0);
    COMPUTE_KS(1, 1);

    // ---- Epilogue ----
    const float alpha = *alpha_p;
    float* obase = Out + ((size_t)bz * MDIM + (size_t)bm * BM) * NDIM + (size_t)bn * BN;

    // IMMA outputs: rows rb+lq (+8), cols ni*8 + lr*2 (+1)
    #pragma unroll
    for (int ni = 0; ni < 8; ni++) {
        int c0 = ni * 8 + lr * 2;
        float2 v0;
        v0.x = __half2float(__float2half_rn(alpha * (float)macc[ni][0]));
        v0.y = __half2float(__float2half_rn(alpha * (float)macc[ni][1]));
        *(float2*)(obase + (size_t)(rb + lq) * NDIM + c0) = v0;
        float2 v1;
        v1.x = __half2float(__float2half_rn(alpha * (float)macc[ni][2]));
        v1.y = __half2float(__float2half_rn(alpha * (float)macc[ni][3]));
        *(float2*)(obase + (size_t)(rb + lq + 8) * NDIM + c0) = v1;
    }

    // dp4a outputs: rows rb + g + 4*mi, cols 64 + j + 8*ni
    #pragma unroll
    for (int mi = 0; mi < 4; mi++) {
        float* orow = obase + (size_t)(rb + g + 4 * mi) * NDIM;
        #pragma unroll
        for (int ni = 0; ni < 8; ni++) {
            int col = 64 + j + 8 * ni;
            orow[col] = __half2float(__float2half_rn(alpha * (float)dacc[mi][ni]));
        }
    }
    #undef COMPUTE_KS
}

extern "C" void kernel_launch(void* const* d_in, const int* in_sizes, int n_in,
                              void* d_out, int out_size) {
    // alpha is the size-1 input; the two large tensors are a then b in index order.
    int ai = -1, bi = -1, si = -1;
    for (int i = 0; i < n_in; i++) {
        if (in_sizes[i] == 1) { si = i; }
        else if (ai < 0)      { ai = i; }
        else                  { bi = i; }
    }
    const int*   a     = (const int*)d_in[ai];
    const int*   b     = (const int*)d_in[bi];
    const float* alpha = (const float*)d_in[si];
    float*       out   = (float*)d_out;

    dim3 grid(NDIM / BN, MDIM / BM, BATCH);   // (8, 8, 64)
    dim3 block(256);
    bmm_s8_pipe_kernel<<<grid, block>>>(a, b, alpha, out);
}